// round 12
// baseline (speedup 1.0000x reference)
#include <cuda_runtime.h>
#include <cuda_bf16.h>
#include <cstdint>

#define DIMC   256
#define NHEADS 8
#define HDIM   32
#define MAXN   10240   // padded: loaders never read past row 10239
#define MAXE   524288

// Scratch (no cudaMalloc allowed).
__device__ float g_q[MAXN * DIMC];
__device__ float g_k[MAXN * DIMC];
__device__ float g_v[MAXN * DIMC];
__device__ float g_acc[MAXN * DIMC];

// CSR by destination node.
__device__ int g_deg[MAXN];
__device__ int g_rowptr[MAXN + 1];
__device__ int g_cursor[MAXN];
__device__ int g_csr[MAXE];          // src node ids grouped by dst

// Pre-split bf16 hi/lo operands in the swizzled smem image.
__device__ float4 gx_s  [MAXN * 64];
__device__ float4 gacc_s[MAXN * 64];
__device__ float4 gw_s  [4 * 256 * 64];

// ---------------------------------------------------------------------------
// bf16 split helpers
// ---------------------------------------------------------------------------
__device__ __forceinline__ void split_pair(float a, float b,
                                           uint32_t& hp, uint32_t& lp)
{
    __nv_bfloat16 ha = __float2bfloat16(a);
    __nv_bfloat16 hb = __float2bfloat16(b);
    float la = a - __bfloat162float(ha);
    float lb = b - __bfloat162float(hb);
    __nv_bfloat16 la16 = __float2bfloat16(la);
    __nv_bfloat16 lb16 = __float2bfloat16(lb);
    hp = (uint32_t)__bfloat16_as_ushort(ha) | ((uint32_t)__bfloat16_as_ushort(hb) << 16);
    lp = (uint32_t)__bfloat16_as_ushort(la16) | ((uint32_t)__bfloat16_as_ushort(lb16) << 16);
}

__device__ __forceinline__ void mma_bf16(float* c,
    uint32_t a0, uint32_t a1, uint32_t a2, uint32_t a3,
    uint32_t b0, uint32_t b1)
{
    asm volatile(
        "mma.sync.aligned.m16n8k16.row.col.f32.bf16.bf16.f32 "
        "{%0,%1,%2,%3}, {%4,%5,%6,%7}, {%8,%9}, {%0,%1,%2,%3};"
        : "+f"(c[0]), "+f"(c[1]), "+f"(c[2]), "+f"(c[3])
        : "r"(a0), "r"(a1), "r"(a2), "r"(a3), "r"(b0), "r"(b1));
}

__device__ __forceinline__ void cpa16(uint32_t dst, const void* src) {
    asm volatile("cp.async.ca.shared.global [%0], [%1], 16;" :: "r"(dst), "l"(src));
}

// ---------------------------------------------------------------------------
// Split helper (fp32 row-chunk -> swizzled bf16 hi/lo image).
// ---------------------------------------------------------------------------
__device__ __forceinline__ void split_rowchunk(
    const float* __restrict__ src, float4* __restrict__ dst, int r, int c)
{
    const float4* s = reinterpret_cast<const float4*>(src + (size_t)r * DIMC + c * 16);
    float x[16];
    *reinterpret_cast<float4*>(x + 0)  = s[0];
    *reinterpret_cast<float4*>(x + 4)  = s[1];
    *reinterpret_cast<float4*>(x + 8)  = s[2];
    *reinterpret_cast<float4*>(x + 12) = s[3];
    uint32_t hp[8], lp[8];
#pragma unroll
    for (int t = 0; t < 8; t++) split_pair(x[2 * t], x[2 * t + 1], hp[t], lp[t]);
    float4* d = dst + ((size_t)r * 64 + c * 4);
    int sw = r & 3;
#pragma unroll
    for (int s2 = 0; s2 < 4; s2++)
        d[s2 ^ sw] = make_float4(__uint_as_float(hp[s2]), __uint_as_float(hp[s2 + 4]),
                                 __uint_as_float(lp[s2]), __uint_as_float(lp[s2 + 4]));
}

// ---------------------------------------------------------------------------
// Prep kernel: zero(g_deg) + split(x) + split(W*). (zero_acc no longer needed)
// ---------------------------------------------------------------------------
__global__ void __launch_bounds__(256) prep_kernel(
    const float* __restrict__ x,
    const float* __restrict__ Wq, const float* __restrict__ Wk,
    const float* __restrict__ Wv, const float* __restrict__ Wo,
    int N, int zeroBlocks, int splitXBlocks)
{
    int b = blockIdx.x;
    if (b < zeroBlocks) {
        int i = b * 256 + threadIdx.x;
        if (i < N) g_deg[i] = 0;
    } else if (b < zeroBlocks + splitXBlocks) {
        int idx = (b - zeroBlocks) * 256 + threadIdx.x;
        if (idx < N * 16) split_rowchunk(x, gx_s, idx >> 4, idx & 15);
    } else {
        int idx = (b - zeroBlocks - splitXBlocks) * 256 + threadIdx.x;
        if (idx < 4 * 256 * 16) {
            int z = idx >> 12;
            int rcl = idx & 4095;
            const float* srcs[4] = {Wq, Wk, Wv, Wo};
            split_rowchunk(srcs[z], gw_s + (size_t)z * 256 * 64, rcl >> 4, rcl & 15);
        }
    }
}

__global__ void __launch_bounds__(256) split_acc_kernel(int rows) {
    int idx = blockIdx.x * blockDim.x + threadIdx.x;
    if (idx >= rows * 16) return;
    split_rowchunk(g_acc, gacc_s, idx >> 4, idx & 15);
}

// ---------------------------------------------------------------------------
// CSR build: histogram -> scan (single CTA) -> fill.
// ---------------------------------------------------------------------------
__global__ void __launch_bounds__(256) hist_kernel(const int* __restrict__ dst, int E) {
    int e = blockIdx.x * blockDim.x + threadIdx.x;
    if (e < E) atomicAdd(&g_deg[dst[e]], 1);
}

__global__ void __launch_bounds__(1024) scan_kernel(int N) {
    __shared__ int part[1024];
    int t = threadIdx.x;
    int per = (N + 1023) / 1024;
    int base = t * per;
    int sum = 0;
    for (int i = 0; i < per; i++)
        if (base + i < N) sum += g_deg[base + i];
    part[t] = sum;
    __syncthreads();
    for (int off = 1; off < 1024; off <<= 1) {
        int v = (t >= off) ? part[t - off] : 0;
        __syncthreads();
        part[t] += v;
        __syncthreads();
    }
    int run = part[t] - sum;   // exclusive prefix of this chunk
    for (int i = 0; i < per; i++) {
        if (base + i < N) {
            g_rowptr[base + i] = run;
            g_cursor[base + i] = run;
            run += g_deg[base + i];
        }
    }
    if (t == 1023) g_rowptr[N] = part[1023];
}

__global__ void __launch_bounds__(256) fill_kernel(
    const int* __restrict__ src, const int* __restrict__ dst, int E)
{
    int e = blockIdx.x * blockDim.x + threadIdx.x;
    if (e < E) {
        int pos = atomicAdd(&g_cursor[dst[e]], 1);
        g_csr[pos] = src[e];
    }
}

// ---------------------------------------------------------------------------
// 3xBF16 tensor-core GEMM (m16n8k16), 4-stage cp.async pipeline.
// Round-8 proven config: CTA 128x64, 256 threads, 2 CTAs/SM.
// ---------------------------------------------------------------------------
#define BM 128
#define BN 64
#define NCH 16
#define STG 4

__device__ __forceinline__ void gemm_bf16s(
    const float4* __restrict__ Asrc, int M,
    const float4* __restrict__ Bsrc,
    const float* __restrict__ Bv,
    float* __restrict__ C,
    int m0, int n0)
{
    __shared__ float4 As[STG][BM][4];
    __shared__ float4 Bs[STG][BN][4];

    int tid  = threadIdx.x;
    int lane = tid & 31;
    int wid  = tid >> 5;
    int wm = (wid & 3) * 32;
    int wn = (wid >> 2) * 32;
    int gq = lane >> 2;
    int tq = lane & 3;

    int arow = tid >> 1, ahalf = tid & 1;
    const float4* ap = Asrc + (size_t)(m0 + arow) * 64 + ahalf * 2;
    int brow = tid >> 2, bslot = tid & 3;
    const float4* bp = Bsrc + (size_t)(n0 + brow) * 64 + bslot;

    uint32_t sA = (uint32_t)__cvta_generic_to_shared(&As[0][0][0]);
    uint32_t sB = (uint32_t)__cvta_generic_to_shared(&Bs[0][0][0]);
    uint32_t daBase = sA + (uint32_t)((arow * 4 + ahalf * 2) * 16);
    uint32_t dbBase = sB + (uint32_t)((brow * 4 + bslot) * 16);

    float acc[2][4][4];
#pragma unroll
    for (int mi = 0; mi < 2; mi++)
#pragma unroll
        for (int ni = 0; ni < 4; ni++)
#pragma unroll
            for (int j = 0; j < 4; j++) acc[mi][ni][j] = 0.f;

#pragma unroll
    for (int s = 0; s < STG - 1; s++) {
        uint32_t da = daBase + s * (BM * 64);
        uint32_t db = dbBase + s * (BN * 64);
        cpa16(da,      ap + s * 4);
        cpa16(da + 16, ap + s * 4 + 1);
        cpa16(db,      bp + s * 4);
        asm volatile("cp.async.commit_group;");
    }

#pragma unroll 1
    for (int ch = 0; ch < NCH; ch++) {
        asm volatile("cp.async.wait_group %0;" :: "n"(STG - 2) : "memory");
        __syncthreads();
        int st = ch & (STG - 1);

        float4 af0[2], af1[2], bfv[4];
#pragma unroll
        for (int mi = 0; mi < 2; mi++) {
            int r0 = wm + mi * 16 + gq;
            af0[mi] = As[st][r0][tq ^ (r0 & 3)];
            af1[mi] = As[st][r0 + 8][tq ^ (r0 & 3)];
        }
#pragma unroll
        for (int ni = 0; ni < 4; ni++) {
            int rn = wn + ni * 8 + gq;
            bfv[ni] = Bs[st][rn][tq ^ (rn & 3)];
        }

#pragma unroll
        for (int mi = 0; mi < 2; mi++) {
            uint32_t a0h = __float_as_uint(af0[mi].x);
            uint32_t a1h = __float_as_uint(af1[mi].x);
            uint32_t a2h = __float_as_uint(af0[mi].y);
            uint32_t a3h = __float_as_uint(af1[mi].y);
            uint32_t a0l = __float_as_uint(af0[mi].z);
            uint32_t a1l = __float_as_uint(af1[mi].z);
            uint32_t a2l = __float_as_uint(af0[mi].w);
            uint32_t a3l = __float_as_uint(af1[mi].w);
#pragma unroll
            for (int ni = 0; ni < 4; ni++) {
                uint32_t b0h = __float_as_uint(bfv[ni].x);
                uint32_t b1h = __float_as_uint(bfv[ni].y);
                uint32_t b0l = __float_as_uint(bfv[ni].z);
                uint32_t b1l = __float_as_uint(bfv[ni].w);
                mma_bf16(acc[mi][ni], a0h, a1h, a2h, a3h, b0h, b1h);
                mma_bf16(acc[mi][ni], a0h, a1h, a2h, a3h, b0l, b1l);
                mma_bf16(acc[mi][ni], a0l, a1l, a2l, a3l, b0h, b1h);
            }
        }

        int nc = ch + STG - 1;
        if (nc < NCH) {
            int ns = nc & (STG - 1);
            uint32_t da = daBase + ns * (BM * 64);
            uint32_t db = dbBase + ns * (BN * 64);
            cpa16(da,      ap + nc * 4);
            cpa16(da + 16, ap + nc * 4 + 1);
            cpa16(db,      bp + nc * 4);
        }
        asm volatile("cp.async.commit_group;");
    }

#pragma unroll
    for (int mi = 0; mi < 2; mi++) {
#pragma unroll
        for (int ni = 0; ni < 4; ni++) {
            int r0 = m0 + wm + mi * 16 + gq;
            int cc = n0 + wn + ni * 8 + 2 * tq;
            float2 bb = *reinterpret_cast<const float2*>(Bv + cc);
            if (r0 < M) {
                float2 o = make_float2(acc[mi][ni][0] + bb.x,
                                       acc[mi][ni][1] + bb.y);
                *reinterpret_cast<float2*>(C + (size_t)r0 * DIMC + cc) = o;
            }
            if (r0 + 8 < M) {
                float2 o = make_float2(acc[mi][ni][2] + bb.x,
                                       acc[mi][ni][3] + bb.y);
                *reinterpret_cast<float2*>(C + (size_t)(r0 + 8) * DIMC + cc) = o;
            }
        }
    }
}

__global__ void __launch_bounds__(256, 2) gemm_qkv_kernel(
    int M,
    const float* __restrict__ bq, const float* __restrict__ bk,
    const float* __restrict__ bv)
{
    int z = blockIdx.z;
    const float* B = (z == 0) ? bq : (z == 1) ? bk : bv;
    float* C = (z == 0) ? g_q : (z == 1) ? g_k : g_v;
    gemm_bf16s(gx_s, M, gw_s + (size_t)z * 256 * 64, B, C,
               blockIdx.y * BM, blockIdx.x * BN);
}

__global__ void __launch_bounds__(256, 2) gemm_out_kernel(
    int M, const float* __restrict__ bo, float* __restrict__ out)
{
    gemm_bf16s(gacc_s, M, gw_s + (size_t)3 * 256 * 64, bo, out,
               blockIdx.y * BM, blockIdx.x * BN);
}

// ---------------------------------------------------------------------------
// Edge kernel, dst-centric: one warp per destination node.
// k[dst] in registers; per in-edge gather q[src], v[src]; register accumulate;
// single coalesced store. No atomics.
// Lane layout (round-8 style): lane owns elements [4l,4l+4) (head l>>3) and
// [4(l+32), ...) (head l>>3 + 4).
// ---------------------------------------------------------------------------
__global__ void __launch_bounds__(256) edge_csr_kernel(int N)
{
    int node = blockIdx.x * 8 + (threadIdx.x >> 5);
    if (node >= N) return;
    int lane = threadIdx.x & 31;

    const float4* kp = reinterpret_cast<const float4*>(g_k + (size_t)node * DIMC);
    float4 k0 = kp[lane];
    float4 k1 = kp[lane + 32];

    float4 a0 = make_float4(0.f, 0.f, 0.f, 0.f);
    float4 a1 = make_float4(0.f, 0.f, 0.f, 0.f);

    int beg = g_rowptr[node];
    int end = g_rowptr[node + 1];

    const float scale = 0.17677669529663687f;     // 1/sqrt(32)
    const float LOG2E = 1.4426950408889634f;

    if (beg < end) {
        int s = g_csr[beg];
        const float4* qp = reinterpret_cast<const float4*>(g_q + (size_t)s * DIMC);
        const float4* vp = reinterpret_cast<const float4*>(g_v + (size_t)s * DIMC);
        float4 q0 = qp[lane], q1 = qp[lane + 32];
        float4 v0 = vp[lane], v1 = vp[lane + 32];

#pragma unroll 1
        for (int j = beg; j < end; j++) {
            // prefetch next edge's rows (clamped; loads are always safe)
            int s2 = (j + 1 < end) ? g_csr[j + 1] : s;
            const float4* qp2 = reinterpret_cast<const float4*>(g_q + (size_t)s2 * DIMC);
            const float4* vp2 = reinterpret_cast<const float4*>(g_v + (size_t)s2 * DIMC);
            float4 nq0 = qp2[lane], nq1 = qp2[lane + 32];
            float4 nv0 = vp2[lane], nv1 = vp2[lane + 32];

            float p0 = q0.x * k0.x + q0.y * k0.y + q0.z * k0.z + q0.w * k0.w;
            float p1 = q1.x * k1.x + q1.y * k1.y + q1.z * k1.z + q1.w * k1.w;
#pragma unroll
            for (int m = 1; m <= 4; m <<= 1) {
                p0 += __shfl_xor_sync(0xffffffffu, p0, m);
                p1 += __shfl_xor_sync(0xffffffffu, p1, m);
            }
            float sc0 = p0 * scale;     // head lane>>3
            float sc1 = p1 * scale;     // head lane>>3 + 4

            // warp-wide max over heads (every head represented in each lane pairset)
            float mx = fmaxf(sc0, sc1);
#pragma unroll
            for (int m = 1; m <= 16; m <<= 1)
                mx = fmaxf(mx, __shfl_xor_sync(0xffffffffu, mx, m));

            float e0 = exp2f((sc0 - mx) * LOG2E);
            float e1 = exp2f((sc1 - mx) * LOG2E);

            // warp sum of (e0+e1) = 8 * sum over 8 heads
            float t = e0 + e1;
#pragma unroll
            for (int m = 1; m <= 16; m <<= 1)
                t += __shfl_xor_sync(0xffffffffu, t, m);
            float inv = 8.0f / t;

            float w0 = e0 * inv;
            float w1 = e1 * inv;

            a0.x = fmaf(w0, v0.x, a0.x); a0.y = fmaf(w0, v0.y, a0.y);
            a0.z = fmaf(w0, v0.z, a0.z); a0.w = fmaf(w0, v0.w, a0.w);
            a1.x = fmaf(w1, v1.x, a1.x); a1.y = fmaf(w1, v1.y, a1.y);
            a1.z = fmaf(w1, v1.z, a1.z); a1.w = fmaf(w1, v1.w, a1.w);

            q0 = nq0; q1 = nq1; v0 = nv0; v1 = nv1;
        }
    }

    float4* op = reinterpret_cast<float4*>(g_acc + (size_t)node * DIMC);
    op[lane]      = a0;
    op[lane + 32] = a1;
}

// ---------------------------------------------------------------------------
// Launch
// ---------------------------------------------------------------------------
extern "C" void kernel_launch(void* const* d_in, const int* in_sizes, int n_in,
                              void* d_out, int out_size)
{
    const float* x   = (const float*)d_in[0];
    const int*   src = (const int*)  d_in[1];
    const int*   dst = (const int*)  d_in[2];
    const float* Wq  = (const float*)d_in[3];
    const float* bq  = (const float*)d_in[4];
    const float* Wk  = (const float*)d_in[5];
    const float* bk  = (const float*)d_in[6];
    const float* Wv  = (const float*)d_in[7];
    const float* bv  = (const float*)d_in[8];
    const float* Wo  = (const float*)d_in[9];
    const float* bo  = (const float*)d_in[10];
    float* out = (float*)d_out;

    int N = in_sizes[0] / DIMC;
    int E = in_sizes[1];

    int mtiles = (N + BM - 1) / BM;
    int ntiles = DIMC / BN;

    // 1) prep: zero deg + split x + split W
    int zeroBlocks   = (N + 255) / 256;
    int splitXBlocks = (N * 16 + 255) / 256;
    int splitWBlocks = (4 * 256 * 16 + 255) / 256;
    prep_kernel<<<zeroBlocks + splitXBlocks + splitWBlocks, 256>>>(
        x, Wq, Wk, Wv, Wo, N, zeroBlocks, splitXBlocks);

    // 2) CSR build (tiny kernels)
    hist_kernel<<<(E + 255) / 256, 256>>>(dst, E);
    scan_kernel<<<1, 1024>>>(N);
    fill_kernel<<<(E + 255) / 256, 256>>>(src, dst, E);

    // 3) Q/K/V projections
    {
        dim3 grid(ntiles, mtiles, 3);
        gemm_qkv_kernel<<<grid, 256>>>(N, bq, bk, bv);
    }

    // 4) dst-centric attention (no atomics)
    edge_csr_kernel<<<(N + 7) / 8, 256>>>(N);

    // 5) split aggregated features, output projection
    split_acc_kernel<<<(N * 16 + 255) / 256, 256>>>(N);
    {
        dim3 grid(ntiles, mtiles, 1);
        gemm_out_kernel<<<grid, 256>>>(N, bo, out);
    }
}

// round 13
// speedup vs baseline: 1.1101x; 1.1101x over previous
#include <cuda_runtime.h>
#include <cuda_bf16.h>
#include <cuda_fp16.h>
#include <cstdint>

#define DIMC   256
#define NHEADS 8
#define HDIM   32
#define MAXN   10240   // padded: loaders never read past row 10239
#define MAXE   524288

// Scratch (no cudaMalloc allowed).
__device__ __half g_qh[MAXN * DIMC];   // q in fp16 (gathered per edge)
__device__ float  g_k [MAXN * DIMC];   // k in fp32 (read once per node)
__device__ __half g_vh[MAXN * DIMC];   // v in fp16 (gathered per edge)

// CSR by destination node. g_deg is zero at entry of every kernel_launch:
// statically zero-initialized, and fill_kernel re-zeroes it after use.
__device__ int g_deg[MAXN];
__device__ int g_rowptr[MAXN + 1];
__device__ int g_cursor[MAXN];
__device__ int g_csr[MAXE];

// Pre-split bf16 hi/lo operands in the swizzled smem image.
// Per row: 16 k16-chunks x 4 float4 slots (slot index pre-XORed with row&3).
// Slot s float4 = (hiPair[s], hiPair[s+4], loPair[s], loPair[s+4]).
__device__ float4 gx_s  [MAXN * 64];
__device__ float4 gacc_s[MAXN * 64];   // written directly by edge_csr
__device__ float4 gw_s  [4 * 256 * 64];

// ---------------------------------------------------------------------------
// bf16 split helpers
// ---------------------------------------------------------------------------
__device__ __forceinline__ void split_pair(float a, float b,
                                           uint32_t& hp, uint32_t& lp)
{
    __nv_bfloat16 ha = __float2bfloat16(a);
    __nv_bfloat16 hb = __float2bfloat16(b);
    float la = a - __bfloat162float(ha);
    float lb = b - __bfloat162float(hb);
    __nv_bfloat16 la16 = __float2bfloat16(la);
    __nv_bfloat16 lb16 = __float2bfloat16(lb);
    hp = (uint32_t)__bfloat16_as_ushort(ha) | ((uint32_t)__bfloat16_as_ushort(hb) << 16);
    lp = (uint32_t)__bfloat16_as_ushort(la16) | ((uint32_t)__bfloat16_as_ushort(lb16) << 16);
}

__device__ __forceinline__ void mma_bf16(float* c,
    uint32_t a0, uint32_t a1, uint32_t a2, uint32_t a3,
    uint32_t b0, uint32_t b1)
{
    asm volatile(
        "mma.sync.aligned.m16n8k16.row.col.f32.bf16.bf16.f32 "
        "{%0,%1,%2,%3}, {%4,%5,%6,%7}, {%8,%9}, {%0,%1,%2,%3};"
        : "+f"(c[0]), "+f"(c[1]), "+f"(c[2]), "+f"(c[3])
        : "r"(a0), "r"(a1), "r"(a2), "r"(a3), "r"(b0), "r"(b1));
}

__device__ __forceinline__ void cpa16(uint32_t dst, const void* src) {
    asm volatile("cp.async.ca.shared.global [%0], [%1], 16;" :: "r"(dst), "l"(src));
}

// ---------------------------------------------------------------------------
// Split helper (fp32 row-chunk -> swizzled bf16 hi/lo image).
// ---------------------------------------------------------------------------
__device__ __forceinline__ void split_rowchunk(
    const float* __restrict__ src, float4* __restrict__ dst, int r, int c)
{
    const float4* s = reinterpret_cast<const float4*>(src + (size_t)r * DIMC + c * 16);
    float x[16];
    *reinterpret_cast<float4*>(x + 0)  = s[0];
    *reinterpret_cast<float4*>(x + 4)  = s[1];
    *reinterpret_cast<float4*>(x + 8)  = s[2];
    *reinterpret_cast<float4*>(x + 12) = s[3];
    uint32_t hp[8], lp[8];
#pragma unroll
    for (int t = 0; t < 8; t++) split_pair(x[2 * t], x[2 * t + 1], hp[t], lp[t]);
    float4* d = dst + ((size_t)r * 64 + c * 4);
    int sw = r & 3;
#pragma unroll
    for (int s2 = 0; s2 < 4; s2++)
        d[s2 ^ sw] = make_float4(__uint_as_float(hp[s2]), __uint_as_float(hp[s2 + 4]),
                                 __uint_as_float(lp[s2]), __uint_as_float(lp[s2 + 4]));
}

// ---------------------------------------------------------------------------
// Prep kernel: split(x) + split(W*) + dst-histogram, one launch.
// (g_deg is guaranteed zero at entry — see fill_kernel.)
// ---------------------------------------------------------------------------
__global__ void __launch_bounds__(256) prep_kernel(
    const float* __restrict__ x,
    const float* __restrict__ Wq, const float* __restrict__ Wk,
    const float* __restrict__ Wv, const float* __restrict__ Wo,
    const int* __restrict__ dst,
    int N, int E, int splitXBlocks, int splitWBlocks)
{
    int b = blockIdx.x;
    if (b < splitXBlocks) {
        int idx = b * 256 + threadIdx.x;
        if (idx < N * 16) split_rowchunk(x, gx_s, idx >> 4, idx & 15);
    } else if (b < splitXBlocks + splitWBlocks) {
        int idx = (b - splitXBlocks) * 256 + threadIdx.x;
        if (idx < 4 * 256 * 16) {
            int z = idx >> 12;
            int rcl = idx & 4095;
            const float* srcs[4] = {Wq, Wk, Wv, Wo};
            split_rowchunk(srcs[z], gw_s + (size_t)z * 256 * 64, rcl >> 4, rcl & 15);
        }
    } else {
        int e = (b - splitXBlocks - splitWBlocks) * 256 + threadIdx.x;
        if (e < E) atomicAdd(&g_deg[dst[e]], 1);
    }
}

// ---------------------------------------------------------------------------
// CSR build: scan (single CTA) -> fill (+ re-zero g_deg for the next call).
// ---------------------------------------------------------------------------
__global__ void __launch_bounds__(1024) scan_kernel(int N) {
    __shared__ int part[1024];
    int t = threadIdx.x;
    int per = (N + 1023) / 1024;
    int base = t * per;
    int sum = 0;
    for (int i = 0; i < per; i++)
        if (base + i < N) sum += g_deg[base + i];
    part[t] = sum;
    __syncthreads();
    for (int off = 1; off < 1024; off <<= 1) {
        int v = (t >= off) ? part[t - off] : 0;
        __syncthreads();
        part[t] += v;
        __syncthreads();
    }
    int run = part[t] - sum;
    for (int i = 0; i < per; i++) {
        if (base + i < N) {
            g_rowptr[base + i] = run;
            g_cursor[base + i] = run;
            run += g_deg[base + i];
        }
    }
    if (t == 1023) g_rowptr[N] = part[1023];
}

__global__ void __launch_bounds__(256) fill_kernel(
    const int* __restrict__ src, const int* __restrict__ dst,
    int E, int fillBlocks)
{
    int b = blockIdx.x;
    if (b < fillBlocks) {
        int e = b * 256 + threadIdx.x;
        if (e < E) {
            int pos = atomicAdd(&g_cursor[dst[e]], 1);
            g_csr[pos] = src[e];
        }
    } else {
        // restore g_deg = 0 for the next kernel_launch (graph replay safe)
        int i = (b - fillBlocks) * 256 + threadIdx.x;
        if (i < MAXN) g_deg[i] = 0;
    }
}

// ---------------------------------------------------------------------------
// 3xBF16 tensor-core GEMM (m16n8k16), 4-stage cp.async pipeline.
// Round-8 proven config: CTA 128x64, 256 threads, 2 CTAs/SM.
// OUT_HALF selects fp16 vs fp32 epilogue stores.
// ---------------------------------------------------------------------------
#define BM 128
#define BN 64
#define NCH 16
#define STG 4

template<bool OUT_HALF>
__device__ __forceinline__ void gemm_bf16s(
    const float4* __restrict__ Asrc, int M,
    const float4* __restrict__ Bsrc,
    const float* __restrict__ Bv,
    void* __restrict__ Cv,
    int m0, int n0)
{
    __shared__ float4 As[STG][BM][4];
    __shared__ float4 Bs[STG][BN][4];

    int tid  = threadIdx.x;
    int lane = tid & 31;
    int wid  = tid >> 5;
    int wm = (wid & 3) * 32;
    int wn = (wid >> 2) * 32;
    int gq = lane >> 2;
    int tq = lane & 3;

    int arow = tid >> 1, ahalf = tid & 1;
    const float4* ap = Asrc + (size_t)(m0 + arow) * 64 + ahalf * 2;
    int brow = tid >> 2, bslot = tid & 3;
    const float4* bp = Bsrc + (size_t)(n0 + brow) * 64 + bslot;

    uint32_t sA = (uint32_t)__cvta_generic_to_shared(&As[0][0][0]);
    uint32_t sB = (uint32_t)__cvta_generic_to_shared(&Bs[0][0][0]);
    uint32_t daBase = sA + (uint32_t)((arow * 4 + ahalf * 2) * 16);
    uint32_t dbBase = sB + (uint32_t)((brow * 4 + bslot) * 16);

    float acc[2][4][4];
#pragma unroll
    for (int mi = 0; mi < 2; mi++)
#pragma unroll
        for (int ni = 0; ni < 4; ni++)
#pragma unroll
            for (int j = 0; j < 4; j++) acc[mi][ni][j] = 0.f;

#pragma unroll
    for (int s = 0; s < STG - 1; s++) {
        uint32_t da = daBase + s * (BM * 64);
        uint32_t db = dbBase + s * (BN * 64);
        cpa16(da,      ap + s * 4);
        cpa16(da + 16, ap + s * 4 + 1);
        cpa16(db,      bp + s * 4);
        asm volatile("cp.async.commit_group;");
    }

#pragma unroll 1
    for (int ch = 0; ch < NCH; ch++) {
        asm volatile("cp.async.wait_group %0;" :: "n"(STG - 2) : "memory");
        __syncthreads();
        int st = ch & (STG - 1);

        float4 af0[2], af1[2], bfv[4];
#pragma unroll
        for (int mi = 0; mi < 2; mi++) {
            int r0 = wm + mi * 16 + gq;
            af0[mi] = As[st][r0][tq ^ (r0 & 3)];
            af1[mi] = As[st][r0 + 8][tq ^ (r0 & 3)];
        }
#pragma unroll
        for (int ni = 0; ni < 4; ni++) {
            int rn = wn + ni * 8 + gq;
            bfv[ni] = Bs[st][rn][tq ^ (rn & 3)];
        }

#pragma unroll
        for (int mi = 0; mi < 2; mi++) {
            uint32_t a0h = __float_as_uint(af0[mi].x);
            uint32_t a1h = __float_as_uint(af1[mi].x);
            uint32_t a2h = __float_as_uint(af0[mi].y);
            uint32_t a3h = __float_as_uint(af1[mi].y);
            uint32_t a0l = __float_as_uint(af0[mi].z);
            uint32_t a1l = __float_as_uint(af1[mi].z);
            uint32_t a2l = __float_as_uint(af0[mi].w);
            uint32_t a3l = __float_as_uint(af1[mi].w);
#pragma unroll
            for (int ni = 0; ni < 4; ni++) {
                uint32_t b0h = __float_as_uint(bfv[ni].x);
                uint32_t b1h = __float_as_uint(bfv[ni].y);
                uint32_t b0l = __float_as_uint(bfv[ni].z);
                uint32_t b1l = __float_as_uint(bfv[ni].w);
                mma_bf16(acc[mi][ni], a0h, a1h, a2h, a3h, b0h, b1h);
                mma_bf16(acc[mi][ni], a0h, a1h, a2h, a3h, b0l, b1l);
                mma_bf16(acc[mi][ni], a0l, a1l, a2l, a3l, b0h, b1h);
            }
        }

        int nc = ch + STG - 1;
        if (nc < NCH) {
            int ns = nc & (STG - 1);
            uint32_t da = daBase + ns * (BM * 64);
            uint32_t db = dbBase + ns * (BN * 64);
            cpa16(da,      ap + nc * 4);
            cpa16(da + 16, ap + nc * 4 + 1);
            cpa16(db,      bp + nc * 4);
        }
        asm volatile("cp.async.commit_group;");
    }

#pragma unroll
    for (int mi = 0; mi < 2; mi++) {
#pragma unroll
        for (int ni = 0; ni < 4; ni++) {
            int r0 = m0 + wm + mi * 16 + gq;
            int cc = n0 + wn + ni * 8 + 2 * tq;
            float2 bb = *reinterpret_cast<const float2*>(Bv + cc);
            float2 o0 = make_float2(acc[mi][ni][0] + bb.x, acc[mi][ni][1] + bb.y);
            float2 o1 = make_float2(acc[mi][ni][2] + bb.x, acc[mi][ni][3] + bb.y);
            if (OUT_HALF) {
                __half* C = (__half*)Cv;
                if (r0 < M)
                    *reinterpret_cast<__half2*>(C + (size_t)r0 * DIMC + cc) =
                        __floats2half2_rn(o0.x, o0.y);
                if (r0 + 8 < M)
                    *reinterpret_cast<__half2*>(C + (size_t)(r0 + 8) * DIMC + cc) =
                        __floats2half2_rn(o1.x, o1.y);
            } else {
                float* C = (float*)Cv;
                if (r0 < M)
                    *reinterpret_cast<float2*>(C + (size_t)r0 * DIMC + cc) = o0;
                if (r0 + 8 < M)
                    *reinterpret_cast<float2*>(C + (size_t)(r0 + 8) * DIMC + cc) = o1;
            }
        }
    }
}

__global__ void __launch_bounds__(256, 2) gemm_qkv_kernel(
    int M,
    const float* __restrict__ bq, const float* __restrict__ bk,
    const float* __restrict__ bv)
{
    int z = blockIdx.z;
    int m0 = blockIdx.y * BM, n0 = blockIdx.x * BN;
    if (z == 0)
        gemm_bf16s<true >(gx_s, M, gw_s,                         bq, g_qh, m0, n0);
    else if (z == 1)
        gemm_bf16s<false>(gx_s, M, gw_s + (size_t)1 * 256 * 64,  bk, g_k,  m0, n0);
    else
        gemm_bf16s<true >(gx_s, M, gw_s + (size_t)2 * 256 * 64,  bv, g_vh, m0, n0);
}

__global__ void __launch_bounds__(256, 2) gemm_out_kernel(
    int M, const float* __restrict__ bo, float* __restrict__ out)
{
    gemm_bf16s<false>(gacc_s, M, gw_s + (size_t)3 * 256 * 64, bo, out,
                      blockIdx.y * BM, blockIdx.x * BN);
}

// ---------------------------------------------------------------------------
// Edge kernel, dst-centric: one warp per destination node, fp16 q/v gathers,
// fp32 k. Epilogue writes the swizzled bf16 hi/lo split image directly.
// Lane l owns elements [4l,4l+4) and [4(l+32),4(l+32)+4).
// ---------------------------------------------------------------------------
__device__ __forceinline__ float4 h4_to_f4(uint2 u) {
    __half2 a = *reinterpret_cast<__half2*>(&u.x);
    __half2 b = *reinterpret_cast<__half2*>(&u.y);
    float2 fa = __half22float2(a);
    float2 fb = __half22float2(b);
    return make_float4(fa.x, fa.y, fb.x, fb.y);
}

// Write one half-row (4 consecutive elements per lane = 2 bf16-pairs) into the
// split image for chunk c = base_chunk + (lane>>2).
__device__ __forceinline__ void write_split_half(
    int row, int lane, int base_chunk, float4 a)
{
    uint32_t hpA, lpA, hpB, lpB;
    split_pair(a.x, a.y, hpA, lpA);     // pair t = 2*(lane&3)
    split_pair(a.z, a.w, hpB, lpB);     // pair t+1
    uint32_t ehpA = __shfl_xor_sync(0xffffffffu, hpA, 2);
    uint32_t elpA = __shfl_xor_sync(0xffffffffu, lpA, 2);
    uint32_t ehpB = __shfl_xor_sync(0xffffffffu, hpB, 2);
    uint32_t elpB = __shfl_xor_sync(0xffffffffu, lpB, 2);
    int c = base_chunk + (lane >> 2);
    bool low = (lane & 2) == 0;
    int s = low ? 2 * (lane & 3) : 2 * (lane & 3) - 3;   // {0,2} or {1,3}
    float4 slot = low
        ? make_float4(__uint_as_float(hpA), __uint_as_float(ehpA),
                      __uint_as_float(lpA), __uint_as_float(elpA))
        : make_float4(__uint_as_float(ehpB), __uint_as_float(hpB),
                      __uint_as_float(elpB), __uint_as_float(lpB));
    gacc_s[(size_t)row * 64 + c * 4 + (s ^ (row & 3))] = slot;
}

__global__ void __launch_bounds__(256) edge_csr_kernel(int N)
{
    int node = blockIdx.x * 8 + (threadIdx.x >> 5);
    if (node >= N) return;
    int lane = threadIdx.x & 31;

    const float4* kp = reinterpret_cast<const float4*>(g_k + (size_t)node * DIMC);
    float4 k0 = kp[lane];
    float4 k1 = kp[lane + 32];

    float4 a0 = make_float4(0.f, 0.f, 0.f, 0.f);
    float4 a1 = make_float4(0.f, 0.f, 0.f, 0.f);

    int beg = g_rowptr[node];
    int end = g_rowptr[node + 1];

    const float scale = 0.17677669529663687f;     // 1/sqrt(32)
    const float LOG2E = 1.4426950408889634f;

    if (beg < end) {
        int s = g_csr[beg];
        const uint2* qp = reinterpret_cast<const uint2*>(g_qh + (size_t)s * DIMC);
        const uint2* vp = reinterpret_cast<const uint2*>(g_vh + (size_t)s * DIMC);
        uint2 qr0 = qp[lane], qr1 = qp[lane + 32];
        uint2 vr0 = vp[lane], vr1 = vp[lane + 32];

#pragma unroll 1
        for (int j = beg; j < end; j++) {
            int s2 = (j + 1 < end) ? g_csr[j + 1] : s;
            const uint2* qp2 = reinterpret_cast<const uint2*>(g_qh + (size_t)s2 * DIMC);
            const uint2* vp2 = reinterpret_cast<const uint2*>(g_vh + (size_t)s2 * DIMC);
            uint2 nq0 = qp2[lane], nq1 = qp2[lane + 32];
            uint2 nv0 = vp2[lane], nv1 = vp2[lane + 32];

            float4 q0 = h4_to_f4(qr0), q1 = h4_to_f4(qr1);

            float p0 = q0.x * k0.x + q0.y * k0.y + q0.z * k0.z + q0.w * k0.w;
            float p1 = q1.x * k1.x + q1.y * k1.y + q1.z * k1.z + q1.w * k1.w;
#pragma unroll
            for (int m = 1; m <= 4; m <<= 1) {
                p0 += __shfl_xor_sync(0xffffffffu, p0, m);
                p1 += __shfl_xor_sync(0xffffffffu, p1, m);
            }
            float sc0 = p0 * scale;
            float sc1 = p1 * scale;

            float mx = fmaxf(sc0, sc1);
#pragma unroll
            for (int m = 1; m <= 16; m <<= 1)
                mx = fmaxf(mx, __shfl_xor_sync(0xffffffffu, mx, m));

            float e0 = exp2f((sc0 - mx) * LOG2E);
            float e1 = exp2f((sc1 - mx) * LOG2E);

            float t = e0 + e1;
#pragma unroll
            for (int m = 1; m <= 16; m <<= 1)
                t += __shfl_xor_sync(0xffffffffu, t, m);
            float inv = 8.0f / t;

            float w0 = e0 * inv;
            float w1 = e1 * inv;

            float4 v0 = h4_to_f4(vr0), v1 = h4_to_f4(vr1);
            a0.x = fmaf(w0, v0.x, a0.x); a0.y = fmaf(w0, v0.y, a0.y);
            a0.z = fmaf(w0, v0.z, a0.z); a0.w = fmaf(w0, v0.w, a0.w);
            a1.x = fmaf(w1, v1.x, a1.x); a1.y = fmaf(w1, v1.y, a1.y);
            a1.z = fmaf(w1, v1.z, a1.z); a1.w = fmaf(w1, v1.w, a1.w);

            qr0 = nq0; qr1 = nq1; vr0 = nv0; vr1 = nv1;
        }
    }

    // Fused split epilogue (replaces g_acc store + split_acc kernel).
    write_split_half(node, lane, 0, a0);   // chunks 0..7
    write_split_half(node, lane, 8, a1);   // chunks 8..15
}

// ---------------------------------------------------------------------------
// Launch
// ---------------------------------------------------------------------------
extern "C" void kernel_launch(void* const* d_in, const int* in_sizes, int n_in,
                              void* d_out, int out_size)
{
    const float* x   = (const float*)d_in[0];
    const int*   src = (const int*)  d_in[1];
    const int*   dst = (const int*)  d_in[2];
    const float* Wq  = (const float*)d_in[3];
    const float* bq  = (const float*)d_in[4];
    const float* Wk  = (const float*)d_in[5];
    const float* bk  = (const float*)d_in[6];
    const float* Wv  = (const float*)d_in[7];
    const float* bv  = (const float*)d_in[8];
    const float* Wo  = (const float*)d_in[9];
    const float* bo  = (const float*)d_in[10];
    float* out = (float*)d_out;

    int N = in_sizes[0] / DIMC;
    int E = in_sizes[1];

    int mtiles = (N + BM - 1) / BM;
    int ntiles = DIMC / BN;

    // 1) prep: split x + split W + dst histogram (one launch)
    int splitXBlocks = (N * 16 + 255) / 256;
    int splitWBlocks = (4 * 256 * 16 + 255) / 256;
    int histBlocks   = (E + 255) / 256;
    prep_kernel<<<splitXBlocks + splitWBlocks + histBlocks, 256>>>(
        x, Wq, Wk, Wv, Wo, dst, N, E, splitXBlocks, splitWBlocks);

    // 2) CSR build
    scan_kernel<<<1, 1024>>>(N);
    int fillBlocks = (E + 255) / 256;
    int zeroDegBlocks = (MAXN + 255) / 256;
    fill_kernel<<<fillBlocks + zeroDegBlocks, 256>>>(src, dst, E, fillBlocks);

    // 3) Q/K/V projections (q,v fp16; k fp32)
    {
        dim3 grid(ntiles, mtiles, 3);
        gemm_qkv_kernel<<<grid, 256>>>(N, bq, bk, bv);
    }

    // 4) dst-centric attention, fused split epilogue
    edge_csr_kernel<<<(N + 7) / 8, 256>>>(N);

    // 5) output projection
    {
        dim3 grid(ntiles, mtiles, 1);
        gemm_out_kernel<<<grid, 256>>>(N, bo, out);
    }
}